// round 15
// baseline (speedup 1.0000x reference)
#include <cuda_runtime.h>
#include <cuda_fp16.h>
#include <cstdint>

#define NTOK 8192
#define HDIM 1024
#define FDIM 4096
#define NEXP 8

#define BN 128
#define BK 64          /* halves per k-tile */
#define NSTAGE 3
#define ROW 144        /* A: bytes per 64-half row (128B + 16B pad) */
#define BROW 272       /* B: bytes per 128-half row (256B + 16B pad) */
#define B_ST (BK * BROW)               /* 17408 */

#define OFF_TOK  0
#define OFF_WGT  512
#define OFF_BIAS 1536
#define OFF_A    2048

// ---------------- scratch (device globals: no allocation allowed) ----------
__device__ int    g_cnt[NEXP];
__device__ int    g_off[NEXP];
__device__ int    g_tok[NEXP * NTOK];
__device__ float  g_wgt[NEXP * NTOK];
__device__ __half g_hbuf[(size_t)(2 * NTOK) * FDIM];            // 128 MB fp16
__device__ __half g_xh  [(size_t)NTOK * HDIM];                  // fp16 x
__device__ __half g_w1h [(size_t)NEXP * (size_t)HDIM * FDIM];   // fp16 W1 [e][h][f]
__device__ __half g_w2h [(size_t)NEXP * (size_t)FDIM * HDIM];   // fp16 W2 [e][f][h]

// ---------------- helpers ---------------------------------------------------
__device__ __forceinline__ uint32_t smem_u32(const void* p) {
    uint32_t a;
    asm("{ .reg .u64 t; cvta.to.shared.u64 t, %1; cvt.u32.u64 %0, t; }" : "=r"(a) : "l"(p));
    return a;
}

__device__ __forceinline__ void mma_f16(float* c, const uint32_t* a, const uint32_t* b) {
    asm("mma.sync.aligned.m16n8k16.row.col.f32.f16.f16.f32 "
        "{%0,%1,%2,%3}, {%4,%5,%6,%7}, {%8,%9}, {%0,%1,%2,%3};"
        : "+f"(c[0]), "+f"(c[1]), "+f"(c[2]), "+f"(c[3])
        : "r"(a[0]), "r"(a[1]), "r"(a[2]), "r"(a[3]),
          "r"(b[0]), "r"(b[1]));
}

#define LDSM4(r0, r1, r2, r3, addr) \
    asm volatile("ldmatrix.sync.aligned.m8n8.x4.shared.b16 {%0,%1,%2,%3}, [%4];" \
                 : "=r"(r0), "=r"(r1), "=r"(r2), "=r"(r3) : "r"(addr))

#define LDSM4T(r0, r1, r2, r3, addr) \
    asm volatile("ldmatrix.sync.aligned.m8n8.x4.trans.shared.b16 {%0,%1,%2,%3}, [%4];" \
                 : "=r"(r0), "=r"(r1), "=r"(r2), "=r"(r3) : "r"(addr))

__device__ __forceinline__ float gelu_exact(float v) {
    return 0.5f * v * (1.0f + erff(v * 0.70710678118654752440f));
}

#define CP16(dst, src) \
    asm volatile("cp.async.cg.shared.global [%0], [%1], 16;" \
                 :: "r"((uint32_t)(dst)), "l"(__cvta_generic_to_global(src)))
#define CP_COMMIT() asm volatile("cp.async.commit_group;" ::: "memory")

// convert 8 fp32 -> 8 fp16 (two float4 loads, one uint4 store)
__device__ __forceinline__ void cvt8(const float4* __restrict__ src4, size_t hidx,
                                     __half* __restrict__ dst) {
    float4 a0 = src4[hidx / 4];
    float4 a1 = src4[hidx / 4 + 1];
    __half2 h[4];
    h[0] = __floats2half2_rn(a0.x, a0.y);
    h[1] = __floats2half2_rn(a0.z, a0.w);
    h[2] = __floats2half2_rn(a1.x, a1.y);
    h[3] = __floats2half2_rn(a1.z, a1.w);
    *(uint4*)(dst + hidx) = *(uint4*)h;
}

// ---------------- prep kernel: fused router+xcvt | W1 cvt -------------------
#define PREP_RTR 1024
#define PREP_W1  (PREP_RTR + 2048)

__global__ void prep_kernel(const float* __restrict__ x,
                            const float* __restrict__ grad,
                            const float* __restrict__ Wr,
                            const float* __restrict__ br,
                            const float* __restrict__ W1) {
    const int bid = blockIdx.x;
    const int tid = threadIdx.x;

    if (bid < PREP_RTR) {
        // ---- fused router + x->fp16: 8 tokens per block (one per warp) ----
        __shared__ float wr_s[NEXP * HDIM];     // Wr transposed [e][h], 32KB
        for (int h = tid; h < HDIM; h += 256) {
            float4 w0 = *(const float4*)(Wr + h * NEXP);
            float4 w1 = *(const float4*)(Wr + h * NEXP + 4);
            wr_s[0 * HDIM + h] = w0.x;  wr_s[1 * HDIM + h] = w0.y;
            wr_s[2 * HDIM + h] = w0.z;  wr_s[3 * HDIM + h] = w0.w;
            wr_s[4 * HDIM + h] = w1.x;  wr_s[5 * HDIM + h] = w1.y;
            wr_s[6 * HDIM + h] = w1.z;  wr_s[7 * HDIM + h] = w1.w;
        }
        __syncthreads();

        const int n = bid * 8 + (tid >> 5);
        const int lane = tid & 31;
        const float4* xrow4 = (const float4*)(x + (size_t)n * HDIM);
        const float4* wr4 = (const float4*)wr_s;
        __half* xhrow = g_xh + (size_t)n * HDIM;

        float acc[NEXP];
        #pragma unroll
        for (int e = 0; e < NEXP; e++) acc[e] = 0.f;

        #pragma unroll
        for (int i = 0; i < 8; i++) {
            int idx = i * 32 + lane;
            float4 xv = xrow4[idx];
            __half2 h2[2];
            h2[0] = __floats2half2_rn(xv.x, xv.y);
            h2[1] = __floats2half2_rn(xv.z, xv.w);
            *(uint2*)(xhrow + idx * 4) = *(uint2*)h2;
            #pragma unroll
            for (int e = 0; e < NEXP; e++) {
                float4 wv = wr4[e * 256 + idx];
                acc[e] = fmaf(xv.x, wv.x, acc[e]);
                acc[e] = fmaf(xv.y, wv.y, acc[e]);
                acc[e] = fmaf(xv.z, wv.z, acc[e]);
                acc[e] = fmaf(xv.w, wv.w, acc[e]);
            }
        }
        #pragma unroll
        for (int e = 0; e < NEXP; e++) {
            #pragma unroll
            for (int off = 16; off > 0; off >>= 1)
                acc[e] += __shfl_xor_sync(0xffffffffu, acc[e], off);
        }
        if (lane == 0) {
            float gv = grad[n];
            float l[NEXP];
            #pragma unroll
            for (int e = 0; e < NEXP; e++)
                l[e] = acc[e] + gv * Wr[HDIM * NEXP + e] + br[e];
            float m = l[0];
            #pragma unroll
            for (int e = 1; e < NEXP; e++) m = fmaxf(m, l[e]);
            float p[NEXP];
            float s = 0.f;
            #pragma unroll
            for (int e = 0; e < NEXP; e++) { p[e] = expf(l[e] - m); s += p[e]; }
            float inv = 1.f / s;
            int i1 = 0;
            #pragma unroll
            for (int e = 1; e < NEXP; e++) if (p[e] > p[i1]) i1 = e;
            int i2 = (i1 == 0) ? 1 : 0;
            #pragma unroll
            for (int e = 0; e < NEXP; e++) if (e != i1 && p[e] > p[i2]) i2 = e;
            int s1 = atomicAdd(&g_cnt[i1], 1);
            g_tok[i1 * NTOK + s1] = n;  g_wgt[i1 * NTOK + s1] = p[i1] * inv;
            int s2 = atomicAdd(&g_cnt[i2], 1);
            g_tok[i2 * NTOK + s2] = n;  g_wgt[i2 * NTOK + s2] = p[i2] * inv;
        }
    } else {
        const int b = bid - PREP_RTR;
        #pragma unroll
        for (int j = 0; j < 8; j++)
            cvt8((const float4*)W1, (size_t)b * 16384 + j * 2048 + tid * 8, g_w1h);
    }
}

__global__ void prefix_kernel() {
    if (threadIdx.x == 0) {
        int s = 0;
        #pragma unroll
        for (int e = 0; e < NEXP; e++) { g_off[e] = s; s += g_cnt[e]; }
    }
}

// ---------------- pipelined grouped GEMM (fp16 HMMA, BK=64, LDSM.T B) -------
// BM = 32*MT. Warp tile (MT*16) x 32.
// A[BM,KDIM] k-major fp16 (gathered rows). B natural layout [k][n] fp16.
// IS_G1: A = g_xh by token, B = g_w1h -> gelu -> g_hbuf; warp 8 converts W2.
// else : A = g_hbuf rows,   B = g_w2h -> w*(.+b2) atomic -> out (fp32)
template<int KDIM, int NSTRIDE, int MT, int NTHREADS, bool IS_G1>
__global__ __launch_bounds__(NTHREADS, 2) void moe_gemm(const float* __restrict__ bias,
                                                        float* __restrict__ out,
                                                        const float* __restrict__ W2src) {
    constexpr int BM_  = 32 * MT;
    constexpr int A_ST = BM_ * ROW;
    constexpr int OFF_B = OFF_A + NSTAGE * A_ST;
    constexpr int NAI  = MT;            /* A cp.async passes (32 rows per pass) */

    const int tid  = threadIdx.x;
    const int warp = tid >> 5;

    if (IS_G1 && warp == 8) {
        // ---- W2 convert warp: 2048 halves per block id (<16384) ----
        const int id = blockIdx.x + gridDim.x * (blockIdx.y + gridDim.y * blockIdx.z);
        if (id < 16384) {
            const int lane = tid & 31;
            #pragma unroll
            for (int j = 0; j < 8; j++)
                cvt8((const float4*)W2src, (size_t)id * 2048 + j * 256 + lane * 8, g_w2h);
        }
        return;
    }

    #define BAR() do { \
        if (IS_G1) asm volatile("bar.sync 1, 256;" ::: "memory"); \
        else __syncthreads(); \
    } while (0)

    const int e = blockIdx.z;
    const int cnt = g_cnt[e];
    const int row0 = blockIdx.y * BM_;
    if (row0 >= cnt) return;
    const int off = g_off[e];
    const int n0 = blockIdx.x * BN;

    extern __shared__ char smem[];
    const uint32_t sb = smem_u32(smem);
    const int lane = tid & 31;
    const int wm = warp >> 2;       // 0..1 (MT*16 rows each)
    const int wn = warp & 3;        // 0..3 (32 cols each)
    const int g  = lane >> 2;       // 0..7
    const int tig = lane & 3;       // 0..3

    int*   tok_s  = (int*)(smem + OFF_TOK);
    float* wgt_s  = (float*)(smem + OFF_WGT);
    float* bias_s = (float*)(smem + OFF_BIAS);

    if (tid < BM_) {
        int gr = row0 + tid;
        int sr = (gr < cnt) ? gr : (cnt - 1);
        tok_s[tid] = g_tok[e * NTOK + sr];
        wgt_s[tid] = g_wgt[e * NTOK + sr];
    }
    if (tid < BN)
        bias_s[tid] = bias[(size_t)e * NSTRIDE + n0 + tid];
    BAR();

    // ---- cp.async geometry (16B = 8 halves per chunk) ----
    // A: NAI passes: rows (tid>>3)+32i, 16B chunk tid&7 (128B = 64 halves per row)
    const __half* aptr[NAI];
    #pragma unroll
    for (int i = 0; i < NAI; i++) {
        int r = (tid >> 3) + i * 32;
        if (IS_G1) {
            aptr[i] = g_xh + (size_t)tok_s[r] * HDIM + (tid & 7) * 8;
        } else {
            int gr = row0 + r;
            int sr = (gr < cnt) ? gr : (cnt - 1);
            aptr[i] = g_hbuf + (size_t)(off + sr) * FDIM + (tid & 7) * 8;
        }
    }
    const uint32_t dA0 = sb + OFF_A + (tid >> 3) * ROW + (tid & 7) * 16;

    // B: natural [k][n]: 4 passes: k-rows (tid>>4)+16i, chunk tid&15
    const __half* wsrc = IS_G1 ? g_w1h : g_w2h;
    const __half* bptr = wsrc + (size_t)e * HDIM * FDIM
                       + (size_t)(tid >> 4) * NSTRIDE + n0 + (tid & 15) * 8;
    const uint32_t dB0 = sb + OFF_B + (tid >> 4) * BROW + (tid & 15) * 16;

    // ---- LDSM per-lane base addresses ----
    const uint32_t a_off = sb + OFF_A + (uint32_t)(wm * (MT * 16) + (lane & 15)) * ROW
                         + ((lane >> 4) & 1) * 16;
    const uint32_t b_off = sb + OFF_B + (uint32_t)(lane & 15) * BROW
                         + (uint32_t)(wn * 32 + ((lane >> 4) & 1) * 8) * 2;

    constexpr int NK = KDIM / BK;

    #define LOAD_TILE(T) do { \
        const int _s = (T) % NSTAGE; \
        _Pragma("unroll") \
        for (int _i = 0; _i < NAI; _i++) \
            CP16(dA0 + _s * A_ST + _i * (32 * ROW), aptr[_i] + (T) * BK); \
        const uint32_t _db = dB0 + _s * B_ST; \
        _Pragma("unroll") \
        for (int _i = 0; _i < 4; _i++) \
            CP16(_db + _i * (16 * BROW), \
                 bptr + ((size_t)(T) * BK + _i * 16) * NSTRIDE); \
        CP_COMMIT(); \
    } while (0)

    float acc[MT][4][4];
    #pragma unroll
    for (int mt = 0; mt < MT; mt++)
        #pragma unroll
        for (int nt = 0; nt < 4; nt++)
            #pragma unroll
            for (int i = 0; i < 4; i++) acc[mt][nt][i] = 0.f;

    LOAD_TILE(0);
    LOAD_TILE(1);

    for (int kt = 0; kt < NK; ++kt) {
        if (kt + 1 < NK) {
            asm volatile("cp.async.wait_group 1;" ::: "memory");
        } else {
            asm volatile("cp.async.wait_group 0;" ::: "memory");
        }
        BAR();
        if (kt + 2 < NK) LOAD_TILE(kt + 2);

        const int s = kt % NSTAGE;
        const uint32_t sA = a_off + s * A_ST;
        const uint32_t sB = b_off + s * B_ST;

        #pragma unroll
        for (int ks = 0; ks < 4; ks++) {           // four k16 steps per 64-half tile
            uint32_t a[MT][4], b[4][2];
            #pragma unroll
            for (int mt = 0; mt < MT; mt++)
                LDSM4(a[mt][0], a[mt][1], a[mt][2], a[mt][3],
                      sA + mt * (16 * ROW) + ks * 32);
            #pragma unroll
            for (int j = 0; j < 2; j++)
                LDSM4T(b[2 * j][0], b[2 * j][1], b[2 * j + 1][0], b[2 * j + 1][1],
                       sB + ks * (16 * BROW) + j * 32);
            #pragma unroll
            for (int mt = 0; mt < MT; mt++)
                #pragma unroll
                for (int nt = 0; nt < 4; nt++)
                    mma_f16(acc[mt][nt], a[mt], b[nt]);
        }
    }
    #undef LOAD_TILE
    BAR();

    // ---- epilogue ----
    #pragma unroll
    for (int mt = 0; mt < MT; mt++) {
        #pragma unroll
        for (int half = 0; half < 2; half++) {
            const int rl = wm * (MT * 16) + mt * 16 + g + half * 8;
            const int gr = row0 + rl;
            if (gr < cnt) {
                if (IS_G1) {
                    __half* hrow = g_hbuf + (size_t)(off + gr) * FDIM + n0 + wn * 32;
                    #pragma unroll
                    for (int nt = 0; nt < 4; nt++) {
                        int c = nt * 8 + tig * 2;
                        float v0 = gelu_exact(acc[mt][nt][half * 2 + 0] + bias_s[wn * 32 + c]);
                        float v1 = gelu_exact(acc[mt][nt][half * 2 + 1] + bias_s[wn * 32 + c + 1]);
                        *(__half2*)(hrow + c) = __floats2half2_rn(v0, v1);
                    }
                } else {
                    const int   tok = tok_s[rl];
                    const float w   = wgt_s[rl];
                    float* orow = out + (size_t)tok * HDIM + n0 + wn * 32;
                    #pragma unroll
                    for (int nt = 0; nt < 4; nt++) {
                        int c = nt * 8 + tig * 2;
                        float v0 = w * (acc[mt][nt][half * 2 + 0] + bias_s[wn * 32 + c]);
                        float v1 = w * (acc[mt][nt][half * 2 + 1] + bias_s[wn * 32 + c + 1]);
                        atomicAdd(orow + c,     v0);
                        atomicAdd(orow + c + 1, v1);
                    }
                }
            }
        }
    }
    #undef BAR
}

// ---------------- launch -----------------------------------------------------
extern "C" void kernel_launch(void* const* d_in, const int* in_sizes, int n_in,
                              void* d_out, int out_size) {
    const float* x    = (const float*)d_in[0];
    const float* grad = (const float*)d_in[1];
    const float* Wr   = (const float*)d_in[2];
    const float* br   = (const float*)d_in[3];
    const float* W1   = (const float*)d_in[4];
    const float* b1   = (const float*)d_in[5];
    const float* W2   = (const float*)d_in[6];
    const float* b2   = (const float*)d_in[7];
    float* out = (float*)d_out;

    constexpr int SMEM_G1 = OFF_A + NSTAGE * (128 * ROW) + NSTAGE * B_ST;  /* 109568 */
    constexpr int SMEM_G2 = OFF_A + NSTAGE * (64 * ROW) + NSTAGE * B_ST;   /* 81920 */

    cudaFuncSetAttribute((const void*)moe_gemm<HDIM, FDIM, 4, 288, true>,
                         cudaFuncAttributeMaxDynamicSharedMemorySize, SMEM_G1);
    cudaFuncSetAttribute((const void*)moe_gemm<FDIM, HDIM, 2, 256, false>,
                         cudaFuncAttributeMaxDynamicSharedMemorySize, SMEM_G2);

    void* cntp; cudaGetSymbolAddress(&cntp, g_cnt);
    cudaMemsetAsync(cntp, 0, NEXP * sizeof(int));
    cudaMemsetAsync(out, 0, (size_t)out_size * sizeof(float));

    prep_kernel<<<PREP_W1, 256>>>(x, grad, Wr, br, W1);
    prefix_kernel<<<1, 32>>>();

    // gemm1: BM=128 -> grid (32, 64, 8) = 16384 blocks (matches W2 convert ids)
    moe_gemm<HDIM, FDIM, 4, 288, true>
        <<<dim3(FDIM / BN, NTOK / 128, NEXP), 288, SMEM_G1>>>(b1, nullptr, W2);
    // gemm2: BM=64
    moe_gemm<FDIM, HDIM, 2, 256, false>
        <<<dim3(HDIM / BN, NTOK / 64, NEXP), 256, SMEM_G2>>>(b2, out, nullptr);
}

// round 16
// speedup vs baseline: 1.0971x; 1.0971x over previous
#include <cuda_runtime.h>
#include <cuda_fp16.h>
#include <cstdint>

#define NTOK 8192
#define HDIM 1024
#define FDIM 4096
#define NEXP 8

#define BN 128
#define BK 32          /* halves per k-tile */
#define NSTAGE 4
#define ROW 80         /* A: bytes per 32-half row (64B + 16B pad) */
#define BROW 272       /* B: bytes per 128-half row (256B + 16B pad) */
#define B_ST (BK * BROW)               /* 8704 */

#define OFF_TOK  0
#define OFF_WGT  512
#define OFF_BIAS 1536
#define OFF_A    2048

// ---------------- scratch (device globals: no allocation allowed) ----------
__device__ int    g_cnt[NEXP];
__device__ int    g_off[NEXP];
__device__ int    g_tok[NEXP * NTOK];
__device__ float  g_wgt[NEXP * NTOK];
__device__ __half g_hbuf[(size_t)(2 * NTOK) * FDIM];            // 128 MB fp16
__device__ __half g_xh  [(size_t)NTOK * HDIM];                  // fp16 x
__device__ __half g_w1h [(size_t)NEXP * (size_t)HDIM * FDIM];   // fp16 W1 [e][h][f]
__device__ __half g_w2h [(size_t)NEXP * (size_t)FDIM * HDIM];   // fp16 W2 [e][f][h]

// ---------------- helpers ---------------------------------------------------
__device__ __forceinline__ uint32_t smem_u32(const void* p) {
    uint32_t a;
    asm("{ .reg .u64 t; cvta.to.shared.u64 t, %1; cvt.u32.u64 %0, t; }" : "=r"(a) : "l"(p));
    return a;
}

__device__ __forceinline__ void mma_f16(float* c, const uint32_t* a, const uint32_t* b) {
    asm("mma.sync.aligned.m16n8k16.row.col.f32.f16.f16.f32 "
        "{%0,%1,%2,%3}, {%4,%5,%6,%7}, {%8,%9}, {%0,%1,%2,%3};"
        : "+f"(c[0]), "+f"(c[1]), "+f"(c[2]), "+f"(c[3])
        : "r"(a[0]), "r"(a[1]), "r"(a[2]), "r"(a[3]),
          "r"(b[0]), "r"(b[1]));
}

#define LDSM4(r0, r1, r2, r3, addr) \
    asm volatile("ldmatrix.sync.aligned.m8n8.x4.shared.b16 {%0,%1,%2,%3}, [%4];" \
                 : "=r"(r0), "=r"(r1), "=r"(r2), "=r"(r3) : "r"(addr))

#define LDSM4T(r0, r1, r2, r3, addr) \
    asm volatile("ldmatrix.sync.aligned.m8n8.x4.trans.shared.b16 {%0,%1,%2,%3}, [%4];" \
                 : "=r"(r0), "=r"(r1), "=r"(r2), "=r"(r3) : "r"(addr))

__device__ __forceinline__ float gelu_exact(float v) {
    return 0.5f * v * (1.0f + erff(v * 0.70710678118654752440f));
}

#define CP16(dst, src) \
    asm volatile("cp.async.cg.shared.global [%0], [%1], 16;" \
                 :: "r"((uint32_t)(dst)), "l"(__cvta_generic_to_global(src)))
#define CP_COMMIT() asm volatile("cp.async.commit_group;" ::: "memory")

// convert 8 fp32 -> 8 fp16 (two float4 loads, one uint4 store)
__device__ __forceinline__ void cvt8(const float4* __restrict__ src4, size_t hidx,
                                     __half* __restrict__ dst) {
    float4 a0 = src4[hidx / 4];
    float4 a1 = src4[hidx / 4 + 1];
    __half2 h[4];
    h[0] = __floats2half2_rn(a0.x, a0.y);
    h[1] = __floats2half2_rn(a0.z, a0.w);
    h[2] = __floats2half2_rn(a1.x, a1.y);
    h[3] = __floats2half2_rn(a1.z, a1.w);
    *(uint4*)(dst + hidx) = *(uint4*)h;
}

// ---------------- prep kernel: fused router+xcvt | W1 cvt -------------------
#define PREP_RTR 1024
#define PREP_W1  (PREP_RTR + 2048)

__global__ void prep_kernel(const float* __restrict__ x,
                            const float* __restrict__ grad,
                            const float* __restrict__ Wr,
                            const float* __restrict__ br,
                            const float* __restrict__ W1) {
    const int bid = blockIdx.x;
    const int tid = threadIdx.x;

    if (bid < PREP_RTR) {
        // ---- fused router + x->fp16: 8 tokens per block (one per warp) ----
        __shared__ float wr_s[NEXP * HDIM];     // Wr transposed [e][h], 32KB
        for (int h = tid; h < HDIM; h += 256) {
            float4 w0 = *(const float4*)(Wr + h * NEXP);
            float4 w1 = *(const float4*)(Wr + h * NEXP + 4);
            wr_s[0 * HDIM + h] = w0.x;  wr_s[1 * HDIM + h] = w0.y;
            wr_s[2 * HDIM + h] = w0.z;  wr_s[3 * HDIM + h] = w0.w;
            wr_s[4 * HDIM + h] = w1.x;  wr_s[5 * HDIM + h] = w1.y;
            wr_s[6 * HDIM + h] = w1.z;  wr_s[7 * HDIM + h] = w1.w;
        }
        __syncthreads();

        const int n = bid * 8 + (tid >> 5);
        const int lane = tid & 31;
        const float4* xrow4 = (const float4*)(x + (size_t)n * HDIM);
        const float4* wr4 = (const float4*)wr_s;
        __half* xhrow = g_xh + (size_t)n * HDIM;

        float acc[NEXP];
        #pragma unroll
        for (int e = 0; e < NEXP; e++) acc[e] = 0.f;

        #pragma unroll
        for (int i = 0; i < 8; i++) {
            int idx = i * 32 + lane;
            float4 xv = xrow4[idx];
            __half2 h2[2];
            h2[0] = __floats2half2_rn(xv.x, xv.y);
            h2[1] = __floats2half2_rn(xv.z, xv.w);
            *(uint2*)(xhrow + idx * 4) = *(uint2*)h2;
            #pragma unroll
            for (int e = 0; e < NEXP; e++) {
                float4 wv = wr4[e * 256 + idx];
                acc[e] = fmaf(xv.x, wv.x, acc[e]);
                acc[e] = fmaf(xv.y, wv.y, acc[e]);
                acc[e] = fmaf(xv.z, wv.z, acc[e]);
                acc[e] = fmaf(xv.w, wv.w, acc[e]);
            }
        }
        #pragma unroll
        for (int e = 0; e < NEXP; e++) {
            #pragma unroll
            for (int off = 16; off > 0; off >>= 1)
                acc[e] += __shfl_xor_sync(0xffffffffu, acc[e], off);
        }
        if (lane == 0) {
            float gv = grad[n];
            float l[NEXP];
            #pragma unroll
            for (int e = 0; e < NEXP; e++)
                l[e] = acc[e] + gv * Wr[HDIM * NEXP + e] + br[e];
            float m = l[0];
            #pragma unroll
            for (int e = 1; e < NEXP; e++) m = fmaxf(m, l[e]);
            float p[NEXP];
            float s = 0.f;
            #pragma unroll
            for (int e = 0; e < NEXP; e++) { p[e] = expf(l[e] - m); s += p[e]; }
            float inv = 1.f / s;
            int i1 = 0;
            #pragma unroll
            for (int e = 1; e < NEXP; e++) if (p[e] > p[i1]) i1 = e;
            int i2 = (i1 == 0) ? 1 : 0;
            #pragma unroll
            for (int e = 0; e < NEXP; e++) if (e != i1 && p[e] > p[i2]) i2 = e;
            int s1 = atomicAdd(&g_cnt[i1], 1);
            g_tok[i1 * NTOK + s1] = n;  g_wgt[i1 * NTOK + s1] = p[i1] * inv;
            int s2 = atomicAdd(&g_cnt[i2], 1);
            g_tok[i2 * NTOK + s2] = n;  g_wgt[i2 * NTOK + s2] = p[i2] * inv;
        }
    } else {
        const int b = bid - PREP_RTR;
        #pragma unroll
        for (int j = 0; j < 8; j++)
            cvt8((const float4*)W1, (size_t)b * 16384 + j * 2048 + tid * 8, g_w1h);
    }
}

__global__ void prefix_kernel() {
    if (threadIdx.x == 0) {
        int s = 0;
        #pragma unroll
        for (int e = 0; e < NEXP; e++) { g_off[e] = s; s += g_cnt[e]; }
    }
}

// ---------------- gemm1 (R14 config: BM=128, 288 thr, occ 2) -----------------
// A = g_xh gathered by token, B = g_w1h [k][n] -> gelu -> g_hbuf (fp16)
// warp 8 converts W2 fp32 -> fp16 alongside.
__global__ __launch_bounds__(288, 2) void moe_gemm1(const float* __restrict__ bias,
                                                    const float* __restrict__ W2src) {
    constexpr int MT = 4;
    constexpr int BM_ = 128;
    constexpr int A_ST = BM_ * ROW;
    constexpr int OFF_B = OFF_A + NSTAGE * A_ST;
    constexpr int NAI = 2;

    const int tid  = threadIdx.x;
    const int warp = tid >> 5;

    if (warp == 8) {
        const int id = blockIdx.x + gridDim.x * (blockIdx.y + gridDim.y * blockIdx.z);
        if (id < 16384) {
            const int lane = tid & 31;
            #pragma unroll
            for (int j = 0; j < 8; j++)
                cvt8((const float4*)W2src, (size_t)id * 2048 + j * 256 + lane * 8, g_w2h);
        }
        return;
    }

    #define BAR1() asm volatile("bar.sync 1, 256;" ::: "memory")

    const int e = blockIdx.z;
    const int cnt = g_cnt[e];
    const int row0 = blockIdx.y * BM_;
    if (row0 >= cnt) return;
    const int off = g_off[e];
    const int n0 = blockIdx.x * BN;

    extern __shared__ char smem[];
    const uint32_t sb = smem_u32(smem);
    const int lane = tid & 31;
    const int wm = warp >> 2;
    const int wn = warp & 3;
    const int g  = lane >> 2;
    const int tig = lane & 3;

    int*   tok_s  = (int*)(smem + OFF_TOK);
    float* bias_s = (float*)(smem + OFF_BIAS);

    if (tid < BM_) {
        int gr = row0 + tid;
        int sr = (gr < cnt) ? gr : (cnt - 1);
        tok_s[tid] = g_tok[e * NTOK + sr];
    }
    if (tid < BN)
        bias_s[tid] = bias[(size_t)e * FDIM + n0 + tid];
    BAR1();

    const __half* aptr[NAI];
    #pragma unroll
    for (int i = 0; i < NAI; i++) {
        int r = (tid >> 2) + i * 64;
        aptr[i] = g_xh + (size_t)tok_s[r] * HDIM + (tid & 3) * 8;
    }
    const uint32_t dA0 = sb + OFF_A + (tid >> 2) * ROW + (tid & 3) * 16;

    const __half* bptr = g_w1h + (size_t)e * HDIM * FDIM
                       + (size_t)(tid >> 4) * FDIM + n0 + (tid & 15) * 8;
    const uint32_t dB0 = sb + OFF_B + (tid >> 4) * BROW + (tid & 15) * 16;

    const uint32_t a_off = sb + OFF_A + (uint32_t)(wm * 64 + (lane & 15)) * ROW
                         + ((lane >> 4) & 1) * 16;
    const uint32_t b_off = sb + OFF_B + (uint32_t)(lane & 15) * BROW
                         + (uint32_t)(wn * 32 + ((lane >> 4) & 1) * 8) * 2;

    constexpr int NK = HDIM / BK;

    #define LOAD_TILE1(T) do { \
        const int _s = (T) % NSTAGE; \
        _Pragma("unroll") \
        for (int _i = 0; _i < NAI; _i++) \
            CP16(dA0 + _s * A_ST + _i * (64 * ROW), aptr[_i] + (T) * BK); \
        const uint32_t _db = dB0 + _s * B_ST; \
        _Pragma("unroll") \
        for (int _i = 0; _i < 2; _i++) \
            CP16(_db + _i * (16 * BROW), \
                 bptr + ((size_t)(T) * BK + _i * 16) * FDIM); \
        CP_COMMIT(); \
    } while (0)

    float acc[MT][4][4];
    #pragma unroll
    for (int mt = 0; mt < MT; mt++)
        #pragma unroll
        for (int nt = 0; nt < 4; nt++)
            #pragma unroll
            for (int i = 0; i < 4; i++) acc[mt][nt][i] = 0.f;

    LOAD_TILE1(0);
    LOAD_TILE1(1);
    LOAD_TILE1(2);

    for (int kt = 0; kt < NK; ++kt) {
        if (kt + 3 <= NK) {
            asm volatile("cp.async.wait_group 2;" ::: "memory");
        } else if (kt + 2 == NK) {
            asm volatile("cp.async.wait_group 1;" ::: "memory");
        } else {
            asm volatile("cp.async.wait_group 0;" ::: "memory");
        }
        BAR1();
        if (kt + 3 < NK) LOAD_TILE1(kt + 3);

        const int s = kt % NSTAGE;
        const uint32_t sA = a_off + s * A_ST;
        const uint32_t sB = b_off + s * B_ST;

        #pragma unroll
        for (int ks = 0; ks < 2; ks++) {
            uint32_t a[MT][4], b[4][2];
            #pragma unroll
            for (int mt = 0; mt < MT; mt++)
                LDSM4(a[mt][0], a[mt][1], a[mt][2], a[mt][3],
                      sA + mt * (16 * ROW) + ks * 32);
            #pragma unroll
            for (int j = 0; j < 2; j++)
                LDSM4T(b[2 * j][0], b[2 * j][1], b[2 * j + 1][0], b[2 * j + 1][1],
                       sB + ks * (16 * BROW) + j * 32);
            #pragma unroll
            for (int mt = 0; mt < MT; mt++)
                #pragma unroll
                for (int nt = 0; nt < 4; nt++)
                    mma_f16(acc[mt][nt], a[mt], b[nt]);
        }
    }
    #undef LOAD_TILE1
    BAR1();

    #pragma unroll
    for (int mt = 0; mt < MT; mt++) {
        #pragma unroll
        for (int half = 0; half < 2; half++) {
            const int rl = wm * 64 + mt * 16 + g + half * 8;
            const int gr = row0 + rl;
            if (gr < cnt) {
                __half* hrow = g_hbuf + (size_t)(off + gr) * FDIM + n0 + wn * 32;
                #pragma unroll
                for (int nt = 0; nt < 4; nt++) {
                    int c = nt * 8 + tig * 2;
                    float v0 = gelu_exact(acc[mt][nt][half * 2 + 0] + bias_s[wn * 32 + c]);
                    float v1 = gelu_exact(acc[mt][nt][half * 2 + 1] + bias_s[wn * 32 + c + 1]);
                    *(__half2*)(hrow + c) = __floats2half2_rn(v0, v1);
                }
            }
        }
    }
    #undef BAR1
}

// ---------------- gemm2: 128-thread CTA, occ 4, warp tile 32x64 --------------
// A = g_hbuf rows (contiguous), B = g_w2h [k][n] -> w*(.+b2) atomic -> out
#define G2_NSTAGE 3
#define G2_A_ST (64 * ROW)                                 /* 5120 */
#define G2_OFF_B (OFF_A + G2_NSTAGE * G2_A_ST)             /* 17408 */
#define G2_SMEM (G2_OFF_B + G2_NSTAGE * B_ST)              /* 43520 */

__global__ __launch_bounds__(128, 4) void moe_gemm2(const float* __restrict__ bias,
                                                    float* __restrict__ out) {
    const int e = blockIdx.z;
    const int cnt = g_cnt[e];
    const int row0 = blockIdx.y * 64;
    if (row0 >= cnt) return;
    const int off = g_off[e];
    const int n0 = blockIdx.x * BN;

    extern __shared__ char smem[];
    const uint32_t sb = smem_u32(smem);
    const int tid  = threadIdx.x;
    const int lane = tid & 31;
    const int warp = tid >> 5;
    const int wm = warp >> 1;       // 0..1 (32 rows each)
    const int wn = warp & 1;        // 0..1 (64 cols each)
    const int g  = lane >> 2;
    const int tig = lane & 3;

    int*   tok_s  = (int*)(smem + OFF_TOK);
    float* wgt_s  = (float*)(smem + OFF_WGT);
    float* bias_s = (float*)(smem + OFF_BIAS);

    if (tid < 64) {
        int gr = row0 + tid;
        int sr = (gr < cnt) ? gr : (cnt - 1);
        tok_s[tid] = g_tok[e * NTOK + sr];
        wgt_s[tid] = g_wgt[e * NTOK + sr];
    }
    bias_s[tid] = bias[(size_t)e * HDIM + n0 + tid];
    __syncthreads();

    // A: 2 passes: rows (tid>>2)+32i, chunk tid&3
    const __half* aptr[2];
    #pragma unroll
    for (int i = 0; i < 2; i++) {
        int r = (tid >> 2) + i * 32;
        int gr = row0 + r;
        int sr = (gr < cnt) ? gr : (cnt - 1);
        aptr[i] = g_hbuf + (size_t)(off + sr) * FDIM + (tid & 3) * 8;
    }
    const uint32_t dA0 = sb + OFF_A + (tid >> 2) * ROW + (tid & 3) * 16;

    // B: 4 passes: k-rows (tid>>4)+8i, chunk tid&15
    const __half* bptr = g_w2h + (size_t)e * HDIM * FDIM
                       + (size_t)(tid >> 4) * HDIM + n0 + (tid & 15) * 8;
    const uint32_t dB0 = sb + G2_OFF_B + (tid >> 4) * BROW + (tid & 15) * 16;

    const uint32_t a_off = sb + OFF_A + (uint32_t)(wm * 32 + (lane & 15)) * ROW
                         + ((lane >> 4) & 1) * 16;
    const uint32_t b_off = sb + G2_OFF_B + (uint32_t)(lane & 15) * BROW
                         + (uint32_t)(wn * 64 + ((lane >> 4) & 1) * 8) * 2;

    constexpr int NK = FDIM / BK;

    #define LOAD_TILE2(T) do { \
        const int _s = (T) % G2_NSTAGE; \
        _Pragma("unroll") \
        for (int _i = 0; _i < 2; _i++) \
            CP16(dA0 + _s * G2_A_ST + _i * (32 * ROW), aptr[_i] + (T) * BK); \
        const uint32_t _db = dB0 + _s * B_ST; \
        _Pragma("unroll") \
        for (int _i = 0; _i < 4; _i++) \
            CP16(_db + _i * (8 * BROW), \
                 bptr + ((size_t)(T) * BK + _i * 8) * HDIM); \
        CP_COMMIT(); \
    } while (0)

    float acc[2][8][4];
    #pragma unroll
    for (int mt = 0; mt < 2; mt++)
        #pragma unroll
        for (int nt = 0; nt < 8; nt++)
            #pragma unroll
            for (int i = 0; i < 4; i++) acc[mt][nt][i] = 0.f;

    LOAD_TILE2(0);
    LOAD_TILE2(1);

    for (int kt = 0; kt < NK; ++kt) {
        if (kt + 1 < NK) {
            asm volatile("cp.async.wait_group 1;" ::: "memory");
        } else {
            asm volatile("cp.async.wait_group 0;" ::: "memory");
        }
        __syncthreads();
        if (kt + 2 < NK) LOAD_TILE2(kt + 2);

        const int s = kt % G2_NSTAGE;
        const uint32_t sA = a_off + s * G2_A_ST;
        const uint32_t sB = b_off + s * B_ST;

        #pragma unroll
        for (int ks = 0; ks < 2; ks++) {
            uint32_t a[2][4], b[8][2];
            #pragma unroll
            for (int mt = 0; mt < 2; mt++)
                LDSM4(a[mt][0], a[mt][1], a[mt][2], a[mt][3],
                      sA + mt * (16 * ROW) + ks * 32);
            #pragma unroll
            for (int j = 0; j < 4; j++)
                LDSM4T(b[2 * j][0], b[2 * j][1], b[2 * j + 1][0], b[2 * j + 1][1],
                       sB + ks * (16 * BROW) + j * 32);
            #pragma unroll
            for (int mt = 0; mt < 2; mt++)
                #pragma unroll
                for (int nt = 0; nt < 8; nt++)
                    mma_f16(acc[mt][nt], a[mt], b[nt]);
        }
    }
    #undef LOAD_TILE2
    __syncthreads();

    #pragma unroll
    for (int mt = 0; mt < 2; mt++) {
        #pragma unroll
        for (int half = 0; half < 2; half++) {
            const int rl = wm * 32 + mt * 16 + g + half * 8;
            const int gr = row0 + rl;
            if (gr < cnt) {
                const int   tok = tok_s[rl];
                const float w   = wgt_s[rl];
                float* orow = out + (size_t)tok * HDIM + n0 + wn * 64;
                #pragma unroll
                for (int nt = 0; nt < 8; nt++) {
                    int c = nt * 8 + tig * 2;
                    float v0 = w * (acc[mt][nt][half * 2 + 0] + bias_s[wn * 64 + c]);
                    float v1 = w * (acc[mt][nt][half * 2 + 1] + bias_s[wn * 64 + c + 1]);
                    atomicAdd(orow + c,     v0);
                    atomicAdd(orow + c + 1, v1);
                }
            }
        }
    }
}

// ---------------- launch -----------------------------------------------------
extern "C" void kernel_launch(void* const* d_in, const int* in_sizes, int n_in,
                              void* d_out, int out_size) {
    const float* x    = (const float*)d_in[0];
    const float* grad = (const float*)d_in[1];
    const float* Wr   = (const float*)d_in[2];
    const float* br   = (const float*)d_in[3];
    const float* W1   = (const float*)d_in[4];
    const float* b1   = (const float*)d_in[5];
    const float* W2   = (const float*)d_in[6];
    const float* b2   = (const float*)d_in[7];
    float* out = (float*)d_out;

    constexpr int SMEM_G1 = OFF_A + NSTAGE * (128 * ROW) + NSTAGE * B_ST;  /* 77824 */

    cudaFuncSetAttribute((const void*)moe_gemm1,
                         cudaFuncAttributeMaxDynamicSharedMemorySize, SMEM_G1);
    cudaFuncSetAttribute((const void*)moe_gemm2,
                         cudaFuncAttributeMaxDynamicSharedMemorySize, G2_SMEM);

    void* cntp; cudaGetSymbolAddress(&cntp, g_cnt);
    cudaMemsetAsync(cntp, 0, NEXP * sizeof(int));
    cudaMemsetAsync(out, 0, (size_t)out_size * sizeof(float));

    prep_kernel<<<PREP_W1, 256>>>(x, grad, Wr, br, W1);
    prefix_kernel<<<1, 32>>>();

    moe_gemm1<<<dim3(FDIM / BN, NTOK / 128, NEXP), 288, SMEM_G1>>>(b1, W2);
    moe_gemm2<<<dim3(HDIM / BN, NTOK / 64, NEXP), 128, G2_SMEM>>>(b2, out);
}

// round 17
// speedup vs baseline: 1.1543x; 1.0521x over previous
#include <cuda_runtime.h>
#include <cuda_fp16.h>
#include <cstdint>

#define NTOK 8192
#define HDIM 1024
#define FDIM 4096
#define NEXP 8

#define BM 64
#define BN 128
#define BK 32          /* halves per k-tile */
#define NSTAGE 3
#define ROW 80         /* A: bytes per 32-half row (64B + 16B pad) */
#define BROW 272       /* B: bytes per 128-half row (256B + 16B pad) */
#define A_ST (BM * ROW)                /* 5120 */
#define B_ST (BK * BROW)               /* 8704 */

#define OFF_TOK  0
#define OFF_WGT  512
#define OFF_BIAS 1536
#define OFF_A    2048
#define OFF_B   (OFF_A + NSTAGE * A_ST)           /* 17408 */
#define SMEM_GEMM (OFF_B + NSTAGE * B_ST)         /* 43520 */

// ---------------- scratch (device globals: no allocation allowed) ----------
__device__ int    g_cnt[NEXP];
__device__ int    g_off[NEXP];
__device__ int    g_tok[NEXP * NTOK];
__device__ float  g_wgt[NEXP * NTOK];
__device__ __half g_hbuf[(size_t)(2 * NTOK) * FDIM];            // 128 MB fp16
__device__ __half g_xh  [(size_t)NTOK * HDIM];                  // fp16 x
__device__ __half g_w1h [(size_t)NEXP * (size_t)HDIM * FDIM];   // fp16 W1 [e][h][f]
__device__ __half g_w2h [(size_t)NEXP * (size_t)FDIM * HDIM];   // fp16 W2 [e][f][h]

// ---------------- helpers ---------------------------------------------------
__device__ __forceinline__ uint32_t smem_u32(const void* p) {
    uint32_t a;
    asm("{ .reg .u64 t; cvta.to.shared.u64 t, %1; cvt.u32.u64 %0, t; }" : "=r"(a) : "l"(p));
    return a;
}

__device__ __forceinline__ void mma_f16(float* c, const uint32_t* a, const uint32_t* b) {
    asm("mma.sync.aligned.m16n8k16.row.col.f32.f16.f16.f32 "
        "{%0,%1,%2,%3}, {%4,%5,%6,%7}, {%8,%9}, {%0,%1,%2,%3};"
        : "+f"(c[0]), "+f"(c[1]), "+f"(c[2]), "+f"(c[3])
        : "r"(a[0]), "r"(a[1]), "r"(a[2]), "r"(a[3]),
          "r"(b[0]), "r"(b[1]));
}

#define LDSM4(r0, r1, r2, r3, addr) \
    asm volatile("ldmatrix.sync.aligned.m8n8.x4.shared.b16 {%0,%1,%2,%3}, [%4];" \
                 : "=r"(r0), "=r"(r1), "=r"(r2), "=r"(r3) : "r"(addr))

#define LDSM4T(r0, r1, r2, r3, addr) \
    asm volatile("ldmatrix.sync.aligned.m8n8.x4.trans.shared.b16 {%0,%1,%2,%3}, [%4];" \
                 : "=r"(r0), "=r"(r1), "=r"(r2), "=r"(r3) : "r"(addr))

__device__ __forceinline__ float gelu_exact(float v) {
    return 0.5f * v * (1.0f + erff(v * 0.70710678118654752440f));
}

#define CP16(dst, src) \
    asm volatile("cp.async.cg.shared.global [%0], [%1], 16;" \
                 :: "r"((uint32_t)(dst)), "l"(__cvta_generic_to_global(src)))
#define CP_COMMIT() asm volatile("cp.async.commit_group;" ::: "memory")

// convert 8 fp32 -> 8 fp16 (two float4 loads, one uint4 store)
__device__ __forceinline__ void cvt8(const float4* __restrict__ src4, size_t hidx,
                                     __half* __restrict__ dst) {
    float4 a0 = src4[hidx / 4];
    float4 a1 = src4[hidx / 4 + 1];
    __half2 h[4];
    h[0] = __floats2half2_rn(a0.x, a0.y);
    h[1] = __floats2half2_rn(a0.z, a0.w);
    h[2] = __floats2half2_rn(a1.x, a1.y);
    h[3] = __floats2half2_rn(a1.z, a1.w);
    *(uint4*)(dst + hidx) = *(uint4*)h;
}

// ---------------- prep kernel: fused router+xcvt | W1 cvt -------------------
#define PREP_RTR 1024
#define PREP_W1  (PREP_RTR + 2048)

__global__ void prep_kernel(const float* __restrict__ x,
                            const float* __restrict__ grad,
                            const float* __restrict__ Wr,
                            const float* __restrict__ br,
                            const float* __restrict__ W1) {
    const int bid = blockIdx.x;
    const int tid = threadIdx.x;

    if (bid < PREP_RTR) {
        // ---- fused router + x->fp16: 8 tokens per block (one per warp) ----
        __shared__ float wr_s[NEXP * HDIM];     // Wr transposed [e][h], 32KB
        for (int h = tid; h < HDIM; h += 256) {
            float4 w0 = *(const float4*)(Wr + h * NEXP);
            float4 w1 = *(const float4*)(Wr + h * NEXP + 4);
            wr_s[0 * HDIM + h] = w0.x;  wr_s[1 * HDIM + h] = w0.y;
            wr_s[2 * HDIM + h] = w0.z;  wr_s[3 * HDIM + h] = w0.w;
            wr_s[4 * HDIM + h] = w1.x;  wr_s[5 * HDIM + h] = w1.y;
            wr_s[6 * HDIM + h] = w1.z;  wr_s[7 * HDIM + h] = w1.w;
        }
        __syncthreads();

        const int n = bid * 8 + (tid >> 5);
        const int lane = tid & 31;
        const float4* xrow4 = (const float4*)(x + (size_t)n * HDIM);
        const float4* wr4 = (const float4*)wr_s;
        __half* xhrow = g_xh + (size_t)n * HDIM;

        float acc[NEXP];
        #pragma unroll
        for (int e = 0; e < NEXP; e++) acc[e] = 0.f;

        #pragma unroll
        for (int i = 0; i < 8; i++) {
            int idx = i * 32 + lane;
            float4 xv = xrow4[idx];
            __half2 h2[2];
            h2[0] = __floats2half2_rn(xv.x, xv.y);
            h2[1] = __floats2half2_rn(xv.z, xv.w);
            *(uint2*)(xhrow + idx * 4) = *(uint2*)h2;
            #pragma unroll
            for (int e = 0; e < NEXP; e++) {
                float4 wv = wr4[e * 256 + idx];
                acc[e] = fmaf(xv.x, wv.x, acc[e]);
                acc[e] = fmaf(xv.y, wv.y, acc[e]);
                acc[e] = fmaf(xv.z, wv.z, acc[e]);
                acc[e] = fmaf(xv.w, wv.w, acc[e]);
            }
        }
        #pragma unroll
        for (int e = 0; e < NEXP; e++) {
            #pragma unroll
            for (int off = 16; off > 0; off >>= 1)
                acc[e] += __shfl_xor_sync(0xffffffffu, acc[e], off);
        }
        if (lane == 0) {
            float gv = grad[n];
            float l[NEXP];
            #pragma unroll
            for (int e = 0; e < NEXP; e++)
                l[e] = acc[e] + gv * Wr[HDIM * NEXP + e] + br[e];
            float m = l[0];
            #pragma unroll
            for (int e = 1; e < NEXP; e++) m = fmaxf(m, l[e]);
            float p[NEXP];
            float s = 0.f;
            #pragma unroll
            for (int e = 0; e < NEXP; e++) { p[e] = expf(l[e] - m); s += p[e]; }
            float inv = 1.f / s;
            int i1 = 0;
            #pragma unroll
            for (int e = 1; e < NEXP; e++) if (p[e] > p[i1]) i1 = e;
            int i2 = (i1 == 0) ? 1 : 0;
            #pragma unroll
            for (int e = 0; e < NEXP; e++) if (e != i1 && p[e] > p[i2]) i2 = e;
            int s1 = atomicAdd(&g_cnt[i1], 1);
            g_tok[i1 * NTOK + s1] = n;  g_wgt[i1 * NTOK + s1] = p[i1] * inv;
            int s2 = atomicAdd(&g_cnt[i2], 1);
            g_tok[i2 * NTOK + s2] = n;  g_wgt[i2 * NTOK + s2] = p[i2] * inv;
        }
    } else {
        const int b = bid - PREP_RTR;
        #pragma unroll
        for (int j = 0; j < 8; j++)
            cvt8((const float4*)W1, (size_t)b * 16384 + j * 2048 + tid * 8, g_w1h);
    }
}

__global__ void prefix_kernel() {
    if (threadIdx.x == 0) {
        int s = 0;
        #pragma unroll
        for (int e = 0; e < NEXP; e++) { g_off[e] = s; s += g_cnt[e]; }
    }
}

// ---------------- grouped GEMM: 128-thread CTA, occ 4, warp tile 32x64 ------
// A[64,KDIM] k-major fp16. B natural layout [k][n] fp16.
// IS_G1: A = g_xh gathered by token, B = g_w1h -> gelu -> g_hbuf (fp16);
//        each CTA also converts a 1024-half slice of W2 (fp32 -> fp16) first.
// else : A = g_hbuf rows, B = g_w2h -> w*(.+b2) atomic -> out (fp32)
template<int KDIM, int NSTRIDE, bool IS_G1>
__global__ __launch_bounds__(128, 4) void moe_gemm(const float* __restrict__ bias,
                                                   float* __restrict__ out,
                                                   const float* __restrict__ W2src) {
    const int tid  = threadIdx.x;

    if (IS_G1) {
        // ---- W2 convert micro-slice: 1024 halves per block (grid = 32768) ----
        const size_t id = blockIdx.x + (size_t)gridDim.x * (blockIdx.y + (size_t)gridDim.y * blockIdx.z);
        cvt8((const float4*)W2src, id * 1024 + tid * 8, g_w2h);
    }

    const int e = blockIdx.z;
    const int cnt = g_cnt[e];
    const int row0 = blockIdx.y * BM;
    if (row0 >= cnt) return;
    const int off = g_off[e];
    const int n0 = blockIdx.x * BN;

    extern __shared__ char smem[];
    const uint32_t sb = smem_u32(smem);
    const int lane = tid & 31;
    const int warp = tid >> 5;
    const int wm = warp >> 1;       // 0..1 (32 rows each)
    const int wn = warp & 1;        // 0..1 (64 cols each)
    const int g  = lane >> 2;       // 0..7
    const int tig = lane & 3;       // 0..3

    int*   tok_s  = (int*)(smem + OFF_TOK);
    float* wgt_s  = (float*)(smem + OFF_WGT);
    float* bias_s = (float*)(smem + OFF_BIAS);

    if (tid < BM) {
        int gr = row0 + tid;
        int sr = (gr < cnt) ? gr : (cnt - 1);
        tok_s[tid] = g_tok[e * NTOK + sr];
        wgt_s[tid] = g_wgt[e * NTOK + sr];
    }
    bias_s[tid] = bias[(size_t)e * NSTRIDE + n0 + tid];
    __syncthreads();

    // A: 2 passes: rows (tid>>2)+32i, 16B chunk tid&3
    const __half* aptr[2];
    #pragma unroll
    for (int i = 0; i < 2; i++) {
        int r = (tid >> 2) + i * 32;
        if (IS_G1) {
            aptr[i] = g_xh + (size_t)tok_s[r] * HDIM + (tid & 3) * 8;
        } else {
            int gr = row0 + r;
            int sr = (gr < cnt) ? gr : (cnt - 1);
            aptr[i] = g_hbuf + (size_t)(off + sr) * FDIM + (tid & 3) * 8;
        }
    }
    const uint32_t dA0 = sb + OFF_A + (tid >> 2) * ROW + (tid & 3) * 16;

    // B: natural [k][n]: 4 passes: k-rows (tid>>4)+8i, chunk tid&15
    const __half* wsrc = IS_G1 ? g_w1h : g_w2h;
    const __half* bptr = wsrc + (size_t)e * HDIM * FDIM
                       + (size_t)(tid >> 4) * NSTRIDE + n0 + (tid & 15) * 8;
    const uint32_t dB0 = sb + OFF_B + (tid >> 4) * BROW + (tid & 15) * 16;

    const uint32_t a_off = sb + OFF_A + (uint32_t)(wm * 32 + (lane & 15)) * ROW
                         + ((lane >> 4) & 1) * 16;
    const uint32_t b_off = sb + OFF_B + (uint32_t)(lane & 15) * BROW
                         + (uint32_t)(wn * 64 + ((lane >> 4) & 1) * 8) * 2;

    constexpr int NK = KDIM / BK;

    #define LOAD_TILE(T) do { \
        const int _s = (T) % NSTAGE; \
        _Pragma("unroll") \
        for (int _i = 0; _i < 2; _i++) \
            CP16(dA0 + _s * A_ST + _i * (32 * ROW), aptr[_i] + (T) * BK); \
        const uint32_t _db = dB0 + _s * B_ST; \
        _Pragma("unroll") \
        for (int _i = 0; _i < 4; _i++) \
            CP16(_db + _i * (8 * BROW), \
                 bptr + ((size_t)(T) * BK + _i * 8) * NSTRIDE); \
        CP_COMMIT(); \
    } while (0)

    float acc[2][8][4];
    #pragma unroll
    for (int mt = 0; mt < 2; mt++)
        #pragma unroll
        for (int nt = 0; nt < 8; nt++)
            #pragma unroll
            for (int i = 0; i < 4; i++) acc[mt][nt][i] = 0.f;

    LOAD_TILE(0);
    LOAD_TILE(1);

    for (int kt = 0; kt < NK; ++kt) {
        if (kt + 1 < NK) {
            asm volatile("cp.async.wait_group 1;" ::: "memory");
        } else {
            asm volatile("cp.async.wait_group 0;" ::: "memory");
        }
        __syncthreads();
        if (kt + 2 < NK) LOAD_TILE(kt + 2);

        const int s = kt % NSTAGE;
        const uint32_t sA = a_off + s * A_ST;
        const uint32_t sB = b_off + s * B_ST;

        #pragma unroll
        for (int ks = 0; ks < 2; ks++) {
            uint32_t a[2][4], b[8][2];
            #pragma unroll
            for (int mt = 0; mt < 2; mt++)
                LDSM4(a[mt][0], a[mt][1], a[mt][2], a[mt][3],
                      sA + mt * (16 * ROW) + ks * 32);
            #pragma unroll
            for (int j = 0; j < 4; j++)
                LDSM4T(b[2 * j][0], b[2 * j][1], b[2 * j + 1][0], b[2 * j + 1][1],
                       sB + ks * (16 * BROW) + j * 32);
            #pragma unroll
            for (int mt = 0; mt < 2; mt++)
                #pragma unroll
                for (int nt = 0; nt < 8; nt++)
                    mma_f16(acc[mt][nt], a[mt], b[nt]);
        }
    }
    #undef LOAD_TILE
    __syncthreads();

    // ---- epilogue ----
    #pragma unroll
    for (int mt = 0; mt < 2; mt++) {
        #pragma unroll
        for (int half = 0; half < 2; half++) {
            const int rl = wm * 32 + mt * 16 + g + half * 8;
            const int gr = row0 + rl;
            if (gr < cnt) {
                if (IS_G1) {
                    __half* hrow = g_hbuf + (size_t)(off + gr) * FDIM + n0 + wn * 64;
                    #pragma unroll
                    for (int nt = 0; nt < 8; nt++) {
                        int c = nt * 8 + tig * 2;
                        float v0 = gelu_exact(acc[mt][nt][half * 2 + 0] + bias_s[wn * 64 + c]);
                        float v1 = gelu_exact(acc[mt][nt][half * 2 + 1] + bias_s[wn * 64 + c + 1]);
                        *(__half2*)(hrow + c) = __floats2half2_rn(v0, v1);
                    }
                } else {
                    const int   tok = tok_s[rl];
                    const float w   = wgt_s[rl];
                    float* orow = out + (size_t)tok * HDIM + n0 + wn * 64;
                    #pragma unroll
                    for (int nt = 0; nt < 8; nt++) {
                        int c = nt * 8 + tig * 2;
                        float v0 = w * (acc[mt][nt][half * 2 + 0] + bias_s[wn * 64 + c]);
                        float v1 = w * (acc[mt][nt][half * 2 + 1] + bias_s[wn * 64 + c + 1]);
                        atomicAdd(orow + c,     v0);
                        atomicAdd(orow + c + 1, v1);
                    }
                }
            }
        }
    }
}

// ---------------- launch -----------------------------------------------------
extern "C" void kernel_launch(void* const* d_in, const int* in_sizes, int n_in,
                              void* d_out, int out_size) {
    const float* x    = (const float*)d_in[0];
    const float* grad = (const float*)d_in[1];
    const float* Wr   = (const float*)d_in[2];
    const float* br   = (const float*)d_in[3];
    const float* W1   = (const float*)d_in[4];
    const float* b1   = (const float*)d_in[5];
    const float* W2   = (const float*)d_in[6];
    const float* b2   = (const float*)d_in[7];
    float* out = (float*)d_out;

    cudaFuncSetAttribute((const void*)moe_gemm<HDIM, FDIM, true>,
                         cudaFuncAttributeMaxDynamicSharedMemorySize, SMEM_GEMM);
    cudaFuncSetAttribute((const void*)moe_gemm<FDIM, HDIM, false>,
                         cudaFuncAttributeMaxDynamicSharedMemorySize, SMEM_GEMM);

    void* cntp; cudaGetSymbolAddress(&cntp, g_cnt);
    cudaMemsetAsync(cntp, 0, NEXP * sizeof(int));
    cudaMemsetAsync(out, 0, (size_t)out_size * sizeof(float));

    prep_kernel<<<PREP_W1, 256>>>(x, grad, Wr, br, W1);
    prefix_kernel<<<1, 32>>>();

    // gemm1: grid (32, 128, 8) = 32768 blocks; each converts 1024 W2 halves
    moe_gemm<HDIM, FDIM, true>
        <<<dim3(FDIM / BN, NTOK / BM, NEXP), 128, SMEM_GEMM>>>(b1, nullptr, W2);
    // gemm2: grid (8, 128, 8)
    moe_gemm<FDIM, HDIM, false>
        <<<dim3(HDIM / BN, NTOK / BM, NEXP), 128, SMEM_GEMM>>>(b2, out, nullptr);
}